// round 1
// baseline (speedup 1.0000x reference)
#include <cuda_runtime.h>
#include <cstddef>

#define S_TOTAL 50000
#define T_DAYS  1024
#define JW      32
#define CHUNKS  4
#define CHUNK   (T_DAYS / CHUNKS)
#define TPB     128

typedef unsigned long long u64;

// ---- packed f32x2 helpers (Blackwell sm_103a) ----
__device__ __forceinline__ u64 pack2(float lo, float hi) {
    u64 r; asm("mov.b64 %0, {%1, %2};" : "=l"(r) : "f"(lo), "f"(hi)); return r;
}
__device__ __forceinline__ u64 fma2(u64 a, u64 b, u64 c) {
    u64 d; asm("fma.rn.f32x2 %0, %1, %2, %3;" : "=l"(d) : "l"(a), "l"(b), "l"(c)); return d;
}
__device__ __forceinline__ u64 mul2(u64 a, u64 b) {
    u64 d; asm("mul.rn.f32x2 %0, %1, %2;" : "=l"(d) : "l"(a), "l"(b)); return d;
}
__device__ __forceinline__ u64 add2(u64 a, u64 b) {
    u64 d; asm("add.rn.f32x2 %0, %1, %2;" : "=l"(d) : "l"(a), "l"(b)); return d;
}

__global__ __launch_bounds__(TPB, 2)
void covid_kernel(const float* __restrict__ r_t,
                  const float* __restrict__ warmup,
                  const float* __restrict__ delta,
                  const float* __restrict__ Tser,
                  const float* __restrict__ rho,
                  const float* __restrict__ pi,
                  float* __restrict__ out)
{
    __shared__ u64   s_lr2[CHUNK];   // (ln r[t], ln r[t]) packed, for this chunk
    __shared__ float s_red[TPB];
    __shared__ float s_C2[JW];       // inclusive prefix sums of ln r ending at t0-32..t0-1

    const int tid   = threadIdx.x;
    const int chunk = blockIdx.y;
    const int t0    = chunk * CHUNK;

    // ln(r_t) for this chunk, broadcast-packed
    for (int i = tid; i < CHUNK; i += TPB) {
        float lr = logf(r_t[t0 + i]);
        s_lr2[i] = pack2(lr, lr);
    }

    // Prefix sums of ln(r) needed for closed-form ring init of chunks > 0.
    if (chunk > 0) {
        const int n = t0 - JW;
        float part = 0.f;
        for (int i = tid; i < n; i += TPB) part += logf(r_t[i]);
        s_red[tid] = part;
        __syncthreads();
        if (tid == 0) {
            float base = 0.f;
            #pragma unroll 1
            for (int i = 0; i < TPB; i++) base += s_red[i];
            float c = base;
            #pragma unroll 1
            for (int k = 0; k < JW; k++) { c += logf(r_t[n + k]); s_C2[k] = c; }
        }
    }
    __syncthreads();

    const int gid = blockIdx.x * TPB + tid;
    if (gid >= S_TOTAL / 2) return;
    const int s0 = gid * 2;

    const float d0 = delta[s0],         d1 = delta[s0 + 1];
    const float iT0 = 1.f / Tser[s0],   iT1 = 1.f / Tser[s0 + 1];
    const float rh0 = rho[s0],          rh1 = rho[s0 + 1];
    const u64 invT2  = pack2(iT0, iT1);
    const u64 delta2 = pack2(d0, d1);

    // weights: w[j] = rho * pi[j]  (packed for 2 samples)
    u64 w[JW];
    #pragma unroll
    for (int j = 0; j < JW; j++) {
        float2 p = *(const float2*)&pi[j * S_TOTAL + s0];
        w[j] = pack2(p.x * rh0, p.y * rh1);
    }

    // ring[p] = A_full[t0 + p]  (t0 is a multiple of 32, so position == p)
    u64 ring[JW];
    if (chunk == 0) {
        #pragma unroll
        for (int k = 0; k < JW; k++) {
            float2 a = *(const float2*)&warmup[k * S_TOTAL + s0];
            ring[k] = pack2(a.x, a.y);
        }
    } else {
        const float W0 = warmup[(JW - 1) * S_TOTAL + s0];
        const float W1 = warmup[(JW - 1) * S_TOTAL + s0 + 1];
        const float lnd0 = logf(d0), lnd1 = logf(d1);
        #pragma unroll
        for (int k = 0; k < JW; k++) {
            // A_full[i] = W31 * delta^(i-31) * exp(invT * sum_{tau<=i-32} ln r[tau])
            const float m = (float)(t0 + k - (JW - 1));
            const float c2 = s_C2[k];
            float a0 = W0 * expf(fmaf(m, lnd0, iT0 * c2));
            float a1 = W1 * expf(fmaf(m, lnd1, iT1 * c2));
            ring[k] = pack2(a0, a1);
        }
    }

    // exp(x) cubic: 1 + x(1 + x(1/2 + x/6));  |x| <= 0.027 -> err < fp32 ulp
    const u64 K6 = pack2(1.f / 6.f, 1.f / 6.f);
    const u64 KH = pack2(0.5f, 0.5f);
    const u64 K1 = pack2(1.f, 1.f);

    float* po = out + (size_t)t0 * S_TOTAL + s0;

    for (int tb = 0; tb < CHUNK; tb += JW) {
        #pragma unroll
        for (int u = 0; u < JW; u++) {
            const u64 lr2 = s_lr2[tb + u];
            const u64 x   = mul2(lr2, invT2);
            u64 e = fma2(x, K6, KH);
            e = fma2(x, e, K1);
            e = fma2(x, e, K1);
            const u64 g    = mul2(e, delta2);
            const u64 anew = mul2(ring[(u + JW - 1) & (JW - 1)], g);

            // M[t] = sum_k ring[(u+k)&31] * w[31-k]   (4 accumulator chains)
            u64 acc0 = mul2(ring[(u + 0) & (JW - 1)], w[31]);
            u64 acc1 = mul2(ring[(u + 1) & (JW - 1)], w[30]);
            u64 acc2 = mul2(ring[(u + 2) & (JW - 1)], w[29]);
            u64 acc3 = mul2(ring[(u + 3) & (JW - 1)], w[28]);
            #pragma unroll
            for (int k = 4; k < JW; k += 4) {
                acc0 = fma2(ring[(u + k + 0) & (JW - 1)], w[31 - k], acc0);
                acc1 = fma2(ring[(u + k + 1) & (JW - 1)], w[30 - k], acc1);
                acc2 = fma2(ring[(u + k + 2) & (JW - 1)], w[29 - k], acc2);
                acc3 = fma2(ring[(u + k + 3) & (JW - 1)], w[28 - k], acc3);
            }
            const u64 M = add2(add2(acc0, acc1), add2(acc2, acc3));

            ring[u] = anew;              // A_full[t+32] replaces A_full[t]
            *(u64*)po = M;               // coalesced STG.64, 2 samples
            po += S_TOTAL;
        }
    }
}

extern "C" void kernel_launch(void* const* d_in, const int* in_sizes, int n_in,
                              void* d_out, int out_size)
{
    const float* r_t    = (const float*)d_in[0];
    const float* warmup = (const float*)d_in[1];
    const float* delta  = (const float*)d_in[2];
    const float* Tser   = (const float*)d_in[3];
    const float* rho    = (const float*)d_in[4];
    const float* pi     = (const float*)d_in[5];

    dim3 grid((S_TOTAL / 2 + TPB - 1) / TPB, CHUNKS);   // (196, 4)
    covid_kernel<<<grid, TPB>>>(r_t, warmup, delta, Tser, rho, pi, (float*)d_out);
}

// round 2
// speedup vs baseline: 1.0410x; 1.0410x over previous
#include <cuda_runtime.h>
#include <cstddef>

#define S_TOTAL 50000
#define T_DAYS  1024
#define JW      32
#define CHUNKS  8
#define CHUNK   (T_DAYS / CHUNKS)
#define TPB     128

typedef unsigned long long u64;

// ---- packed f32x2 helpers (Blackwell sm_103a) ----
__device__ __forceinline__ u64 pack2(float lo, float hi) {
    u64 r; asm("mov.b64 %0, {%1, %2};" : "=l"(r) : "f"(lo), "f"(hi)); return r;
}
__device__ __forceinline__ u64 fma2(u64 a, u64 b, u64 c) {
    u64 d; asm("fma.rn.f32x2 %0, %1, %2, %3;" : "=l"(d) : "l"(a), "l"(b), "l"(c)); return d;
}
__device__ __forceinline__ u64 mul2(u64 a, u64 b) {
    u64 d; asm("mul.rn.f32x2 %0, %1, %2;" : "=l"(d) : "l"(a), "l"(b)); return d;
}
__device__ __forceinline__ u64 add2(u64 a, u64 b) {
    u64 d; asm("add.rn.f32x2 %0, %1, %2;" : "=l"(d) : "l"(a), "l"(b)); return d;
}

__global__ __launch_bounds__(TPB, 3)
void covid_kernel(const float* __restrict__ r_t,
                  const float* __restrict__ warmup,
                  const float* __restrict__ delta,
                  const float* __restrict__ Tser,
                  const float* __restrict__ rho,
                  const float* __restrict__ pi,
                  float* __restrict__ out)
{
    __shared__ u64   s_lr2[CHUNK + 1]; // (ln r[t], ln r[t]) packed, +1 pad for prefetch
    __shared__ float s_red[TPB];
    __shared__ float s_C2[JW];         // inclusive prefix sums of ln r ending at t0-32..t0-1

    const int tid   = threadIdx.x;
    const int chunk = blockIdx.y;
    const int t0    = chunk * CHUNK;

    // ln(r_t) for this chunk, broadcast-packed (+1 pad slot)
    for (int i = tid; i < CHUNK + 1; i += TPB) {
        int idx = t0 + i;
        float lr = (idx < T_DAYS) ? logf(r_t[idx]) : 0.f;
        s_lr2[i] = pack2(lr, lr);
    }

    // Prefix sums of ln(r) for closed-form ring init of chunks > 0.
    if (chunk > 0) {
        const int n = t0 - JW;
        float part = 0.f;
        for (int i = tid; i < n; i += TPB) part += logf(r_t[i]);
        s_red[tid] = part;
        __syncthreads();
        if (tid == 0) {
            float base = 0.f;
            #pragma unroll 1
            for (int i = 0; i < TPB; i++) base += s_red[i];
            float c = base;
            #pragma unroll 1
            for (int k = 0; k < JW; k++) { c += logf(r_t[n + k]); s_C2[k] = c; }
        }
    }
    __syncthreads();

    const int gid = blockIdx.x * TPB + tid;
    if (gid >= S_TOTAL / 2) return;
    const int s0 = gid * 2;

    const float d0 = delta[s0],         d1 = delta[s0 + 1];
    const float iT0 = 1.f / Tser[s0],   iT1 = 1.f / Tser[s0 + 1];
    const float rh0 = rho[s0],          rh1 = rho[s0 + 1];

    // g = delta * exp(invT * lr) ~= c0 + lr*(c1 + lr*(c2 + lr*c3))   (cubic, |x|<=0.027)
    const u64 C0 = pack2(d0, d1);
    const u64 C1 = pack2(d0 * iT0, d1 * iT1);
    const u64 C2 = pack2(d0 * iT0 * iT0 * 0.5f, d1 * iT1 * iT1 * 0.5f);
    const u64 C3 = pack2(d0 * iT0 * iT0 * iT0 * (1.f / 6.f),
                         d1 * iT1 * iT1 * iT1 * (1.f / 6.f));

    // weights: w[j] = rho * pi[j]  (packed for 2 samples)
    u64 w[JW];
    #pragma unroll
    for (int j = 0; j < JW; j++) {
        float2 p = *(const float2*)&pi[j * S_TOTAL + s0];
        w[j] = pack2(p.x * rh0, p.y * rh1);
    }

    // ring[p] = A_full[t0 + p]  (t0 is a multiple of 32, so position == p)
    u64 ring[JW];
    if (chunk == 0) {
        #pragma unroll
        for (int k = 0; k < JW; k++) {
            float2 a = *(const float2*)&warmup[k * S_TOTAL + s0];
            ring[k] = pack2(a.x, a.y);
        }
    } else {
        const float W0 = warmup[(JW - 1) * S_TOTAL + s0];
        const float W1 = warmup[(JW - 1) * S_TOTAL + s0 + 1];
        const float lnd0 = logf(d0), lnd1 = logf(d1);
        #pragma unroll
        for (int k = 0; k < JW; k++) {
            // A_full[i] = W31 * delta^(i-31) * exp(invT * sum_{tau<=i-32} ln r[tau])
            const float m = (float)(t0 + k - (JW - 1));
            const float c2 = s_C2[k];
            float a0 = W0 * expf(fmaf(m, lnd0, iT0 * c2));
            float a1 = W1 * expf(fmaf(m, lnd1, iT1 * c2));
            ring[k] = pack2(a0, a1);
        }
    }

    float* po = out + (size_t)t0 * S_TOTAL + s0;

    u64 lr_cur = s_lr2[0];
    for (int tb = 0; tb < CHUNK; tb += JW) {
        #pragma unroll
        for (int u = 0; u < JW; u++) {
            const u64 lr_nxt = s_lr2[tb + u + 1];   // prefetch (LDS lat off crit path)

            // growth factor: 3 fma2 Horner, delta folded in
            u64 g = fma2(C3, lr_cur, C2);
            g = fma2(g, lr_cur, C1);
            g = fma2(g, lr_cur, C0);
            const u64 anew = mul2(ring[(u + JW - 1) & (JW - 1)], g);

            // M[t] = sum_k ring[(u+k)&31] * w[31-k]   (4 accumulator chains)
            u64 acc0 = mul2(ring[(u + 0) & (JW - 1)], w[31]);
            u64 acc1 = mul2(ring[(u + 1) & (JW - 1)], w[30]);
            u64 acc2 = mul2(ring[(u + 2) & (JW - 1)], w[29]);
            u64 acc3 = mul2(ring[(u + 3) & (JW - 1)], w[28]);
            #pragma unroll
            for (int k = 4; k < JW; k += 4) {
                acc0 = fma2(ring[(u + k + 0) & (JW - 1)], w[31 - k], acc0);
                acc1 = fma2(ring[(u + k + 1) & (JW - 1)], w[30 - k], acc1);
                acc2 = fma2(ring[(u + k + 2) & (JW - 1)], w[29 - k], acc2);
                acc3 = fma2(ring[(u + k + 3) & (JW - 1)], w[28 - k], acc3);
            }
            const u64 M = add2(add2(acc0, acc1), add2(acc2, acc3));

            ring[u] = anew;              // A_full[t+32] replaces A_full[t]
            lr_cur  = lr_nxt;
            *(u64*)po = M;               // coalesced STG.64, 2 samples
            po += S_TOTAL;
        }
    }
}

extern "C" void kernel_launch(void* const* d_in, const int* in_sizes, int n_in,
                              void* d_out, int out_size)
{
    const float* r_t    = (const float*)d_in[0];
    const float* warmup = (const float*)d_in[1];
    const float* delta  = (const float*)d_in[2];
    const float* Tser   = (const float*)d_in[3];
    const float* rho    = (const float*)d_in[4];
    const float* pi     = (const float*)d_in[5];

    dim3 grid((S_TOTAL / 2 + TPB - 1) / TPB, CHUNKS);   // (196, 8)
    covid_kernel<<<grid, TPB>>>(r_t, warmup, delta, Tser, rho, pi, (float*)d_out);
}

// round 3
// speedup vs baseline: 1.2193x; 1.1713x over previous
#include <cuda_runtime.h>
#include <cstddef>

#define S_TOTAL 50000
#define T_DAYS  1024
#define JW      32
#define CHUNKS  8
#define CHUNK   (T_DAYS / CHUNKS)
#define TPB     128

typedef unsigned long long u64;

// scratch: (SL[t], SL[t], t, t) per day; SL = inclusive prefix sum of ln r
__device__ float4 g_SLT[T_DAYS];

// ---- packed f32x2 helpers (Blackwell sm_103a) ----
__device__ __forceinline__ u64 pack2(float lo, float hi) {
    u64 r; asm("mov.b64 %0, {%1, %2};" : "=l"(r) : "f"(lo), "f"(hi)); return r;
}
__device__ __forceinline__ u64 fma2(u64 a, u64 b, u64 c) {
    u64 d; asm("fma.rn.f32x2 %0, %1, %2, %3;" : "=l"(d) : "l"(a), "l"(b), "l"(c)); return d;
}
__device__ __forceinline__ u64 mul2(u64 a, u64 b) {
    u64 d; asm("mul.rn.f32x2 %0, %1, %2;" : "=l"(d) : "l"(a), "l"(b)); return d;
}
__device__ __forceinline__ u64 add2(u64 a, u64 b) {
    u64 d; asm("add.rn.f32x2 %0, %1, %2;" : "=l"(d) : "l"(a), "l"(b)); return d;
}
__device__ __forceinline__ float ex2(float x) {
    float r; asm("ex2.approx.f32 %0, %1;" : "=f"(r) : "f"(x)); return r;
}
__device__ __forceinline__ u64 exp2_pk(u64 z) {
    float zl, zh;
    asm("mov.b64 {%0, %1}, %2;" : "=f"(zl), "=f"(zh) : "l"(z));
    return pack2(ex2(zl), ex2(zh));
}

// One-block prep: ln(r_t) prefix sums -> g_SLT
__global__ void prep_kernel(const float* __restrict__ r_t)
{
    __shared__ float s_part[TPB];
    const int tid = threadIdx.x;
    const int PER = T_DAYS / TPB;   // 8
    float v[PER];
    float run = 0.f;
    #pragma unroll
    for (int k = 0; k < PER; k++) { run += logf(r_t[tid * PER + k]); v[k] = run; }
    s_part[tid] = run;
    __syncthreads();
    // Hillis-Steele inclusive scan over the 128 partials
    #pragma unroll
    for (int off = 1; off < TPB; off <<= 1) {
        float add = (tid >= off) ? s_part[tid - off] : 0.f;
        __syncthreads();
        s_part[tid] += add;
        __syncthreads();
    }
    const float excl = (tid > 0) ? s_part[tid - 1] : 0.f;
    #pragma unroll
    for (int k = 0; k < PER; k++) {
        const int t = tid * PER + k;
        const float SL = excl + v[k];
        g_SLT[t] = make_float4(SL, SL, (float)t, (float)t);
    }
}

__global__ __launch_bounds__(TPB, 3)
void covid_kernel(const float* __restrict__ warmup,
                  const float* __restrict__ delta,
                  const float* __restrict__ Tser,
                  const float* __restrict__ rho,
                  const float* __restrict__ pi,
                  float* __restrict__ out)
{
    __shared__ float4 s_slt[CHUNK];     // (SL,SL,t,t) for this chunk
    __shared__ float  s_sli[JW];        // SL[t0-32+p] for ring init (chunk>0)

    const int tid   = threadIdx.x;
    const int chunk = blockIdx.y;
    const int t0    = chunk * CHUNK;

    for (int i = tid; i < CHUNK; i += TPB) s_slt[i] = g_SLT[t0 + i];
    if (chunk > 0 && tid < JW)            s_sli[tid] = g_SLT[t0 - JW + tid].x;
    __syncthreads();

    const int gid = blockIdx.x * TPB + tid;
    if (gid >= S_TOTAL / 2) return;
    const int s0 = gid * 2;

    const float LOG2E = 1.4426950408889634f;
    const float d0 = delta[s0],       d1 = delta[s0 + 1];
    const float iT0 = 1.f / Tser[s0], iT1 = 1.f / Tser[s0 + 1];
    const float rh0 = rho[s0],        rh1 = rho[s0 + 1];
    const float W0 = warmup[(JW - 1) * S_TOTAL + s0];
    const float W1 = warmup[(JW - 1) * S_TOTAL + s0 + 1];

    // z(t) = SL[t]*c1 + t*c2 + c3 ;  A_full[t+32] = exp2(z(t))
    const float c1_0 = iT0 * LOG2E,      c1_1 = iT1 * LOG2E;
    const float c2_0 = logf(d0) * LOG2E, c2_1 = logf(d1) * LOG2E;
    const float c3_0 = logf(W0) * LOG2E + c2_0;
    const float c3_1 = logf(W1) * LOG2E + c2_1;
    const u64 C1 = pack2(c1_0, c1_1);
    const u64 C2 = pack2(c2_0, c2_1);
    const u64 C3 = pack2(c3_0, c3_1);

    // weights: w[j] = rho * pi[j]
    u64 w[JW];
    #pragma unroll
    for (int j = 0; j < JW; j++) {
        float2 p = *(const float2*)&pi[j * S_TOTAL + s0];
        w[j] = pack2(p.x * rh0, p.y * rh1);
    }

    // ring[p] = A_full[t0 + p]
    u64 ring[JW];
    if (chunk == 0) {
        #pragma unroll
        for (int k = 0; k < JW; k++) {
            float2 a = *(const float2*)&warmup[k * S_TOTAL + s0];
            ring[k] = pack2(a.x, a.y);
        }
    } else {
        #pragma unroll
        for (int p = 0; p < JW; p++) {
            const float te = (float)(t0 - JW + p);
            const float sl = s_sli[p];
            const float z0 = fmaf(sl, c1_0, fmaf(te, c2_0, c3_0));
            const float z1 = fmaf(sl, c1_1, fmaf(te, c2_1, c3_1));
            ring[p] = pack2(ex2(z0), ex2(z1));
        }
    }

    float* po = out + (size_t)t0 * S_TOTAL + s0;

    for (int tb = 0; tb < CHUNK; tb += JW) {
        #pragma unroll
        for (int u = 0; u < JW; u++) {
            const float4 slt = s_slt[tb + u];
            const u64 SLv = pack2(slt.x, slt.y);
            const u64 Tv  = pack2(slt.z, slt.w);
            const u64 z   = fma2(SLv, C1, fma2(Tv, C2, C3));
            const u64 anew = exp2_pk(z);                 // A_full[t+32], MUFU pipe

            // M[t] = sum_k ring[(u+k)&31] * w[31-k]   (2 accumulator chains)
            u64 acc0 = mul2(ring[(u + 0) & (JW - 1)], w[31]);
            u64 acc1 = mul2(ring[(u + 1) & (JW - 1)], w[30]);
            #pragma unroll
            for (int k = 2; k < JW; k += 2) {
                acc0 = fma2(ring[(u + k + 0) & (JW - 1)], w[31 - k], acc0);
                acc1 = fma2(ring[(u + k + 1) & (JW - 1)], w[30 - k], acc1);
            }
            const u64 M = add2(acc0, acc1);

            ring[u] = anew;              // A_full[t+32] replaces A_full[t]
            *(u64*)po = M;               // coalesced STG.64
            po += S_TOTAL;
        }
    }
}

extern "C" void kernel_launch(void* const* d_in, const int* in_sizes, int n_in,
                              void* d_out, int out_size)
{
    const float* r_t    = (const float*)d_in[0];
    const float* warmup = (const float*)d_in[1];
    const float* delta  = (const float*)d_in[2];
    const float* Tser   = (const float*)d_in[3];
    const float* rho    = (const float*)d_in[4];
    const float* pi     = (const float*)d_in[5];

    prep_kernel<<<1, TPB>>>(r_t);
    dim3 grid((S_TOTAL / 2 + TPB - 1) / TPB, CHUNKS);   // (196, 8)
    covid_kernel<<<grid, TPB>>>(warmup, delta, Tser, rho, pi, (float*)d_out);
}